// round 2
// baseline (speedup 1.0000x reference)
#include <cuda_runtime.h>
#include <float.h>

#define KMAX   256
#define BMAX   8
#define BINS   1024          // uniform accelerator bins
#define GRIDX  152           // GB300 SM count; 8 CTAs/SM in one wave

// Segment s (s in [0..K]) covers x in [E_lo, E_hi):
//   s = 0      : (-FLT_MAX, c[0],   0,            E[0])      -> low clamp
//   s = 1..K-1 : ( E[s-1],  c[s-1], slope(s-1,s), E[s])      -> interior
//   s = K      : ( E[K-1],  c[K-1], 0,            FLT_MAX)   -> high clamp
__device__ float4 g_seg[BMAX][KMAX + 2];
__device__ float4 g_uni[BMAX][BINS];   // fused: segment covering each bin start
__device__ int    g_sidx[BINS];        // segment index at each bin start (batch-indep)

// ---------------------------------------------------------------------------
// Kernel 1: per-batch CRF curve + packed segment table. Grid = B, 256 threads.
// ---------------------------------------------------------------------------
__global__ void build_segments(const float* __restrict__ w,    // [B, NB]
                               const float* __restrict__ E,    // [K]
                               const float* __restrict__ f0,   // [K]
                               const float* __restrict__ Hb,   // [K, NB]
                               int K, int NB)
{
    const int b = blockIdx.x;
    const int k = threadIdx.x;

    __shared__ float c[KMAX];
    __shared__ float Es[KMAX];

    if (k < K) {
        float acc = f0[k];
        const float* hrow = Hb + (long long)k * NB;
        const float* wrow = w  + (long long)b * NB;
        #pragma unroll 5
        for (int n = 0; n < NB; n++)
            acc = fmaf(hrow[n], wrow[n], acc);
        c[k]  = acc;
        Es[k] = E[k];
    }
    __syncthreads();

    if (k == 0) {
        g_seg[b][0] = make_float4(-FLT_MAX, c[0],      0.0f, Es[0]);
        g_seg[b][K] = make_float4(Es[K - 1], c[K - 1], 0.0f, FLT_MAX);
    }
    if (k >= 1 && k <= K - 1) {
        const float e0 = Es[k - 1], e1 = Es[k];
        const float slope = (c[k] - c[k - 1]) / (e1 - e0);
        g_seg[b][k] = make_float4(e0, c[k - 1], slope, e1);
    }
}

// ---------------------------------------------------------------------------
// Kernel 2: fused uniform table. Grid = (BINS/256, B). Runs after kernel 1.
// g_uni[b][j] = segment covering x = j/BINS;  g_sidx[j] = its index.
// ---------------------------------------------------------------------------
__global__ void build_uniform(const float* __restrict__ E, int K)
{
    const int j = blockIdx.x * blockDim.x + threadIdx.x;
    const int b = blockIdx.y;
    if (j >= BINS) return;
    const float v = (float)j * (1.0f / (float)BINS);
    int lo = 0, hi = K;                 // first index with E[idx] > v
    while (lo < hi) {
        const int mid = (lo + hi) >> 1;
        if (E[mid] <= v) lo = mid + 1; else hi = mid;
    }
    g_uni[b][j] = g_seg[b][lo];
    if (b == 0) g_sidx[j] = lo;
}

// ---------------------------------------------------------------------------
// Kernel 3: streaming apply. Grid = (GRIDX, B), 256 threads, float4 I/O.
// ---------------------------------------------------------------------------
__device__ __forceinline__ float interp1(float x,
                                         const float4* __restrict__ U,
                                         const int*    __restrict__ sidx,
                                         const float4* __restrict__ seg)
{
    int j = (int)(x * (float)BINS);
    j = min(max(j, 0), BINS - 1);
    float4 sg = U[j];                       // common case: one LDS.128
    if (x >= sg.w || x < sg.x) {            // knot between bin start and x (rare)
        int s = sidx[j];
        sg = seg[s];
        while (sg.x > x) sg = seg[--s];     // float-rounding backward guard
        while (x >= sg.w) sg = seg[++s];    // advance past knot(s) in the bin
    }
    return __saturatef(fmaf(x - sg.x, sg.z, sg.y));
}

__device__ __forceinline__ float4 interp4(float4 x,
                                          const float4* __restrict__ U,
                                          const int*    __restrict__ sidx,
                                          const float4* __restrict__ seg)
{
    float4 y;
    y.x = interp1(x.x, U, sidx, seg);
    y.y = interp1(x.y, U, sidx, seg);
    y.z = interp1(x.z, U, sidx, seg);
    y.w = interp1(x.w, U, sidx, seg);
    return y;
}

__global__ void __launch_bounds__(256, 8)
tmo_apply(const float* __restrict__ img, float* __restrict__ out,
          int npix, int K)
{
    __shared__ float4 U_s[BINS];            // 16 KB
    __shared__ int    sidx_s[BINS];         //  4 KB
    __shared__ float4 seg_s[KMAX + 2];      //  4.1 KB

    const int b = blockIdx.y;

    {
        const float4* u = &g_uni[b][0];
        for (int i = threadIdx.x; i < BINS; i += 256) U_s[i] = u[i];
        for (int i = threadIdx.x; i < BINS; i += 256) sidx_s[i] = g_sidx[i];
        const float4* s = &g_seg[b][0];
        for (int i = threadIdx.x; i <= K; i += 256)   seg_s[i] = s[i];
    }
    __syncthreads();

    const long long base = (long long)b * (long long)npix;
    const float4* __restrict__ in4  = (const float4*)(img + base);
    float4*       __restrict__ out4 = (float4*)(out + base);

    const int n4     = npix >> 2;
    const int stride = GRIDX * 256;
    int i = blockIdx.x * 256 + threadIdx.x;

    // 2x unrolled: both LDG.128 issued before any smem work (MLP for DRAM)
    for (; i + stride < n4; i += 2 * stride) {
        const float4 x0 = in4[i];
        const float4 x1 = in4[i + stride];
        out4[i]          = interp4(x0, U_s, sidx_s, seg_s);
        out4[i + stride] = interp4(x1, U_s, sidx_s, seg_s);
    }
    if (i < n4) {
        const float4 x0 = in4[i];
        out4[i] = interp4(x0, U_s, sidx_s, seg_s);
    }

    // scalar tail (npix not divisible by 4)
    if (blockIdx.x == 0) {
        for (int t = (n4 << 2) + threadIdx.x; t < npix; t += 256)
            out[base + t] = interp1(img[base + t], U_s, sidx_s, seg_s);
    }
}

// ---------------------------------------------------------------------------
// Inputs (metadata order): hdr_image [B,C,H,W] f32, weights_w [B,NB] f32,
//                          E_samples [K] f32, f0_mean [K] f32, H_basis [K,NB] f32
// Output: [B,C,H,W] f32
// ---------------------------------------------------------------------------
extern "C" void kernel_launch(void* const* d_in, const int* in_sizes, int n_in,
                              void* d_out, int out_size)
{
    const float* img = (const float*)d_in[0];
    const float* w   = (const float*)d_in[1];
    const float* E   = (const float*)d_in[2];
    const float* f0  = (const float*)d_in[3];
    const float* Hb  = (const float*)d_in[4];
    float* out = (float*)d_out;

    const int K    = in_sizes[2];                 // 256
    const int NB   = in_sizes[4] / K;             // 25
    const int B    = in_sizes[1] / NB;            // 8
    const int npix = in_sizes[0] / B;             // C*H*W = 6,220,800

    build_segments<<<B, 256>>>(w, E, f0, Hb, K, NB);

    dim3 ugrid((BINS + 255) / 256, B);
    build_uniform<<<ugrid, 256>>>(E, K);

    dim3 grid(GRIDX, B);                          // 8 CTAs/SM on 152 SMs
    tmo_apply<<<grid, 256>>>(img, out, npix, K);
}

// round 3
// speedup vs baseline: 1.3224x; 1.3224x over previous
#include <cuda_runtime.h>
#include <float.h>

#define KMAX   256
#define BMAX   8
#define BINS2  2048                 // guide bins; 32 sub-bins each -> 65536 sub-bins
#define SUBS   65536
#define GRIDX  152                  // GB300 SM count; 8 CTAs/SM, one wave

// Exact segment-index machinery (batch-independent):
//   t(x) = clamp((int)(x*65536f), 0, 65535)   -- exact: *2^16 is rounding-free
//   g_guide[j].x = #knots with t(E) <  j*32
//   g_guide[j].y = bitmask of sub-bins (within bin j) containing >=1 knot
// Per batch: g_seg2[b][s] = (slope, offset) with y = slope*x + offset on segment s,
//   s = #{k : E[k] <= x}  (s=0 low clamp, s=K high clamp), offsets built in double.
__device__ int2   g_guide[BINS2];
__device__ float2 g_seg2[BMAX][KMAX + 2];

// ---------------------------------------------------------------------------
// Kernel 1: per-batch CRF curve -> (slope, offset) table. Grid = B, 256 thr.
// ---------------------------------------------------------------------------
__global__ void build_segments(const float* __restrict__ w,    // [B, NB]
                               const float* __restrict__ E,    // [K]
                               const float* __restrict__ f0,   // [K]
                               const float* __restrict__ Hb,   // [K, NB]
                               int K, int NB)
{
    const int b = blockIdx.x;
    const int k = threadIdx.x;

    __shared__ float c[KMAX];
    __shared__ float Es[KMAX];

    if (k < K) {
        float acc = f0[k];
        const float* hrow = Hb + (long long)k * NB;
        const float* wrow = w  + (long long)b * NB;
        #pragma unroll 5
        for (int n = 0; n < NB; n++)
            acc = fmaf(hrow[n], wrow[n], acc);
        c[k]  = acc;
        Es[k] = E[k];
    }
    __syncthreads();

    if (k == 0) {
        g_seg2[b][0] = make_float2(0.0f, c[0]);        // x < E[0]  -> c[0]
        g_seg2[b][K] = make_float2(0.0f, c[K - 1]);    // x >= E[K-1] -> c[K-1]
    }
    if (k >= 1 && k <= K - 1) {
        const double e0 = (double)Es[k - 1], e1 = (double)Es[k];
        const double sl = ((double)c[k] - (double)c[k - 1]) / (e1 - e0);
        const double of = (double)c[k - 1] - sl * e0;   // double: no cancellation
        g_seg2[b][k] = make_float2((float)sl, (float)of);
    }
}

// ---------------------------------------------------------------------------
// Kernel 2: popcount guide (batch-independent). Grid = BINS2/256, 256 thr.
// ---------------------------------------------------------------------------
__global__ void build_guide(const float* __restrict__ E, int K)
{
    __shared__ int tE[KMAX];
    for (int k = threadIdx.x; k < K; k += blockDim.x) {
        int t = (int)(E[k] * 65536.0f);                 // exact
        tE[k] = min(max(t, 0), SUBS - 1);
    }
    __syncthreads();

    const int j = blockIdx.x * blockDim.x + threadIdx.x;
    if (j >= BINS2) return;
    const int lo = j * 32, hi = lo + 32;
    int cnt = 0; unsigned mask = 0u;
    for (int k = 0; k < K; k++) {
        const int t = tE[k];
        cnt  += (t < lo);
        if (t >= lo && t < hi) mask |= 1u << (t - lo);
    }
    g_guide[j] = make_int2(cnt, (int)mask);
}

// ---------------------------------------------------------------------------
// Kernel 3: streaming apply. Grid = (GRIDX, B), 256 threads, float4 I/O.
// ---------------------------------------------------------------------------
__device__ __forceinline__ float interp1(float x,
                                         const int2*   __restrict__ G,
                                         const float2* __restrict__ S,
                                         const float*  __restrict__ Ek,
                                         int K)
{
    int t = (int)(x * 65536.0f);                        // exact floor for x>=0
    t = min(max(t, 0), SUBS - 1);
    const int2 g = G[t >> 5];                           // LDS.64
    const int ts = t & 31;
    const unsigned m = (unsigned)g.y;
    int s = g.x + __popc(m & ((1u << ts) - 1u));        // exact unless knot shares sub-bin
    if (m & (1u << ts)) {                               // rare: p_lane ~0.4%
        while (s < K && Ek[s] <= x) ++s;                // exact resolve
    }
    const float2 so = S[s];                             // LDS.64
    return __saturatef(fmaf(x, so.x, so.y));
}

__device__ __forceinline__ float4 interp4(float4 x,
                                          const int2*   __restrict__ G,
                                          const float2* __restrict__ S,
                                          const float*  __restrict__ Ek,
                                          int K)
{
    float4 y;
    y.x = interp1(x.x, G, S, Ek, K);
    y.y = interp1(x.y, G, S, Ek, K);
    y.z = interp1(x.z, G, S, Ek, K);
    y.w = interp1(x.w, G, S, Ek, K);
    return y;
}

__global__ void __launch_bounds__(256, 8)
tmo_apply(const float* __restrict__ img, float* __restrict__ out,
          const float* __restrict__ E, int npix, int K)
{
    __shared__ int2   G_s[BINS2];        // 16 KB
    __shared__ float2 S_s[KMAX + 2];     //  ~2 KB
    __shared__ float  E_s[KMAX];         //  1 KB

    const int b = blockIdx.y;

    for (int i = threadIdx.x; i < BINS2; i += 256) G_s[i] = g_guide[i];
    {
        const float2* s = &g_seg2[b][0];
        for (int i = threadIdx.x; i <= K; i += 256) S_s[i] = s[i];
        for (int i = threadIdx.x; i < K;  i += 256) E_s[i] = E[i];
    }
    __syncthreads();

    const long long base = (long long)b * (long long)npix;
    const float4* __restrict__ in4  = (const float4*)(img + base);
    float4*       __restrict__ out4 = (float4*)(out + base);

    const int n4     = npix >> 2;
    const int stride = GRIDX * 256;
    int i = blockIdx.x * 256 + threadIdx.x;

    // 4x unrolled: four independent LDG.128 in flight before smem work
    for (; i + 3 * stride < n4; i += 4 * stride) {
        const float4 x0 = in4[i];
        const float4 x1 = in4[i +     stride];
        const float4 x2 = in4[i + 2 * stride];
        const float4 x3 = in4[i + 3 * stride];
        out4[i]              = interp4(x0, G_s, S_s, E_s, K);
        out4[i +     stride] = interp4(x1, G_s, S_s, E_s, K);
        out4[i + 2 * stride] = interp4(x2, G_s, S_s, E_s, K);
        out4[i + 3 * stride] = interp4(x3, G_s, S_s, E_s, K);
    }
    for (; i < n4; i += stride)
        out4[i] = interp4(in4[i], G_s, S_s, E_s, K);

    // scalar tail (npix not divisible by 4)
    if (blockIdx.x == 0) {
        for (int tix = (n4 << 2) + threadIdx.x; tix < npix; tix += 256)
            out[base + tix] = interp1(img[base + tix], G_s, S_s, E_s, K);
    }
}

// ---------------------------------------------------------------------------
// Inputs (metadata order): hdr_image [B,C,H,W] f32, weights_w [B,NB] f32,
//                          E_samples [K] f32, f0_mean [K] f32, H_basis [K,NB] f32
// Output: [B,C,H,W] f32
// ---------------------------------------------------------------------------
extern "C" void kernel_launch(void* const* d_in, const int* in_sizes, int n_in,
                              void* d_out, int out_size)
{
    const float* img = (const float*)d_in[0];
    const float* w   = (const float*)d_in[1];
    const float* E   = (const float*)d_in[2];
    const float* f0  = (const float*)d_in[3];
    const float* Hb  = (const float*)d_in[4];
    float* out = (float*)d_out;

    const int K    = in_sizes[2];                 // 256
    const int NB   = in_sizes[4] / K;             // 25
    const int B    = in_sizes[1] / NB;            // 8
    const int npix = in_sizes[0] / B;             // C*H*W = 6,220,800

    build_segments<<<B, 256>>>(w, E, f0, Hb, K, NB);
    build_guide<<<(BINS2 + 255) / 256, 256>>>(E, K);

    dim3 grid(GRIDX, B);
    tmo_apply<<<grid, 256>>>(img, out, E, npix, K);
}

// round 6
// speedup vs baseline: 1.5869x; 1.2000x over previous
#include <cuda_runtime.h>
#include <float.h>

#define KMAX   256
#define BMAX   8
#define BINS   4096                 // guide bins; 16 sub-bins each -> 65536 sub-bins
#define SUBS   65536
#define GBLK   16                   // guide build blocks (4096 / 256)
#define GRIDX  152                  // GB300 SM count; 8 CTAs/SM, one wave

// Exact segment-index machinery:
//   t(x) = clamp((int)(x*65536f), 0, 65535)  -- exact: *2^16 only shifts exponent
//   g_guide[j] = (cnt << 16) | mask16, where
//     cnt  = #knots with t(E) <  j*16
//     mask bit i = some knot has t(E) == j*16 + i
// Per batch: g_seg2[b][s] = (slope, offset), y = slope*x + offset on segment s,
//   s = #{k : E[k] <= x} (s=0 low clamp, s=K high clamp); offsets built in double.
__device__ unsigned g_guide[BINS];
__device__ float2   g_seg2[BMAX][KMAX + 2];

// ---------------------------------------------------------------------------
// Kernel 1 (merged setup). Grid = B + GBLK, 256 threads.
//   blocks [0, B)        : per-batch segment tables
//   blocks [B, B + GBLK) : packed popcount guide (batch-independent)
// ---------------------------------------------------------------------------
__global__ void setup_tables(const float* __restrict__ w,    // [B, NB]
                             const float* __restrict__ E,    // [K]
                             const float* __restrict__ f0,   // [K]
                             const float* __restrict__ Hb,   // [K, NB]
                             int K, int NB, int B)
{
    const int blk = blockIdx.x;
    const int tid = threadIdx.x;

    if (blk < B) {
        // ---- segment table for batch b = blk ----
        const int b = blk;
        __shared__ float c[KMAX];
        __shared__ float Es[KMAX];

        if (tid < K) {
            float acc = f0[tid];
            const float* hrow = Hb + (long long)tid * NB;
            const float* wrow = w  + (long long)b   * NB;
            #pragma unroll 5
            for (int n = 0; n < NB; n++)
                acc = fmaf(hrow[n], wrow[n], acc);
            c[tid]  = acc;
            Es[tid] = E[tid];
        }
        __syncthreads();

        if (tid == 0) {
            g_seg2[b][0] = make_float2(0.0f, c[0]);       // x <  E[0]
            g_seg2[b][K] = make_float2(0.0f, c[K - 1]);   // x >= E[K-1]
        }
        if (tid >= 1 && tid <= K - 1) {
            const double e0 = (double)Es[tid - 1], e1 = (double)Es[tid];
            const double sl = ((double)c[tid] - (double)c[tid - 1]) / (e1 - e0);
            const double of = (double)c[tid - 1] - sl * e0;
            g_seg2[b][tid] = make_float2((float)sl, (float)of);
        }
    } else {
        // ---- packed guide, bins [(blk-B)*256, +256) ----
        __shared__ int tE[KMAX];
        for (int k = tid; k < K; k += 256) {
            int t = (int)(E[k] * 65536.0f);               // exact
            tE[k] = min(max(t, 0), SUBS - 1);
        }
        __syncthreads();

        const int j = (blk - B) * 256 + tid;
        if (j < BINS) {
            const int lo = j * 16, hi = lo + 16;
            int cnt = 0; unsigned mask = 0u;
            for (int k = 0; k < K; k++) {
                const int t = tE[k];
                cnt += (t < lo);
                if (t >= lo && t < hi) mask |= 1u << (t - lo);
            }
            g_guide[j] = ((unsigned)cnt << 16) | mask;
        }
    }
}

// ---------------------------------------------------------------------------
// Kernel 2: streaming apply. Grid = (GRIDX, B), 256 threads, float4 I/O.
// ---------------------------------------------------------------------------
__device__ __forceinline__ float interp1(float x,
                                         const unsigned* __restrict__ G,
                                         const float2*   __restrict__ S,
                                         const float*    __restrict__ Ek,
                                         int K)
{
    int t = (int)(x * 65536.0f);                          // exact floor for x>=0
    t = min(max(t, 0), SUBS - 1);
    const unsigned e = G[t >> 4];                         // LDS.32 (1 wave)
    const int ts = t & 15;
    const unsigned m = e & 0xFFFFu;
    int s = (int)(e >> 16) + __popc(m & ((1u << ts) - 1u));
    if (m & (1u << ts)) {                                 // knot shares sub-bin: ~0.4%/lane
        while (s < K && Ek[s] <= x) ++s;                  // exact resolve
    }
    const float2 so = S[s];                               // LDS.64
    return __saturatef(fmaf(x, so.x, so.y));
}

__device__ __forceinline__ float4 interp4(float4 x,
                                          const unsigned* __restrict__ G,
                                          const float2*   __restrict__ S,
                                          const float*    __restrict__ Ek,
                                          int K)
{
    float4 y;
    y.x = interp1(x.x, G, S, Ek, K);
    y.y = interp1(x.y, G, S, Ek, K);
    y.z = interp1(x.z, G, S, Ek, K);
    y.w = interp1(x.w, G, S, Ek, K);
    return y;
}

__global__ void __launch_bounds__(256, 8)
tmo_apply(const float* __restrict__ img, float* __restrict__ out,
          const float* __restrict__ E, int npix, int K)
{
    __shared__ unsigned G_s[BINS];       // 16 KB
    __shared__ float2   S_s[KMAX + 2];   //  ~2 KB
    __shared__ float    E_s[KMAX];       //  1 KB

    const int b = blockIdx.y;

    for (int i = threadIdx.x; i < BINS; i += 256) G_s[i] = g_guide[i];
    {
        const float2* s = &g_seg2[b][0];
        for (int i = threadIdx.x; i <= K; i += 256) S_s[i] = s[i];
        for (int i = threadIdx.x; i < K;  i += 256) E_s[i] = E[i];
    }
    __syncthreads();

    const long long base = (long long)b * (long long)npix;
    const float4* __restrict__ in4  = (const float4*)(img + base);
    float4*       __restrict__ out4 = (float4*)(out + base);

    const int n4     = npix >> 2;
    const int stride = GRIDX * 256;
    int i = blockIdx.x * 256 + threadIdx.x;

    // 4x unrolled: four independent LDG.128 in flight before smem work
    for (; i + 3 * stride < n4; i += 4 * stride) {
        const float4 x0 = in4[i];
        const float4 x1 = in4[i +     stride];
        const float4 x2 = in4[i + 2 * stride];
        const float4 x3 = in4[i + 3 * stride];
        out4[i]              = interp4(x0, G_s, S_s, E_s, K);
        out4[i +     stride] = interp4(x1, G_s, S_s, E_s, K);
        out4[i + 2 * stride] = interp4(x2, G_s, S_s, E_s, K);
        out4[i + 3 * stride] = interp4(x3, G_s, S_s, E_s, K);
    }
    for (; i < n4; i += stride)
        out4[i] = interp4(in4[i], G_s, S_s, E_s, K);

    // scalar tail (npix not divisible by 4; empty for this shape)
    if (blockIdx.x == 0) {
        for (int tix = (n4 << 2) + threadIdx.x; tix < npix; tix += 256)
            out[base + tix] = interp1(img[base + tix], G_s, S_s, E_s, K);
    }
}

// ---------------------------------------------------------------------------
// Inputs (metadata order): hdr_image [B,C,H,W] f32, weights_w [B,NB] f32,
//                          E_samples [K] f32, f0_mean [K] f32, H_basis [K,NB] f32
// Output: [B,C,H,W] f32
// ---------------------------------------------------------------------------
extern "C" void kernel_launch(void* const* d_in, const int* in_sizes, int n_in,
                              void* d_out, int out_size)
{
    const float* img = (const float*)d_in[0];
    const float* w   = (const float*)d_in[1];
    const float* E   = (const float*)d_in[2];
    const float* f0  = (const float*)d_in[3];
    const float* Hb  = (const float*)d_in[4];
    float* out = (float*)d_out;

    const int K    = in_sizes[2];                 // 256
    const int NB   = in_sizes[4] / K;             // 25
    const int B    = in_sizes[1] / NB;            // 8
    const int npix = in_sizes[0] / B;             // C*H*W = 6,220,800

    setup_tables<<<B + GBLK, 256>>>(w, E, f0, Hb, K, NB, B);

    dim3 grid(GRIDX, B);
    tmo_apply<<<grid, 256>>>(img, out, E, npix, K);
}